// round 2
// baseline (speedup 1.0000x reference)
#include <cuda_runtime.h>

#define N_NEURON 500000
#define N_EDGE   10000000

// dual-exponential constants (match reference exactly)
#define DT_C     0.1f
#define LAMDA_D  (0.1f / 2.0f)    // DT/TAO_D
#define LAMDA_R  (0.1f / 10.0f)   // DT/TAO_R
#define INV_TAO_D 0.5f            // 1/TAO_D

// scratch: r_new lives here between the two kernels (no cudaMalloc allowed)
__device__ float g_rnew[N_NEURON];

// ---------------------------------------------------------------------------
// Kernel A: per-neuron fused update.
//   Iback_new = Iback + dt_over_tau*(noise - Iback)
//   Ieff      = Iback_new / sqrt_coeff * sig + mu
//   s_new     = s + LAMDA_R*(-s + spike/TAO_D)
//   r_new     = r - LAMDA_D*r + DT*s_new
// Writes r_new to scratch, seeds out = Ieff (accumulator base).
// ---------------------------------------------------------------------------
__global__ void neuron_kernel(const float* __restrict__ Iback,
                              const float* __restrict__ spike,
                              const float* __restrict__ s,
                              const float* __restrict__ r,
                              const float* __restrict__ noise,
                              const float* __restrict__ dt_over_tau,
                              const float* __restrict__ sqrt_coeff,
                              const float* __restrict__ sig,
                              const float* __restrict__ mu,
                              float* __restrict__ out)
{
    int i = blockIdx.x * blockDim.x + threadIdx.x;
    if (i >= N_NEURON) return;

    float dtau = __ldg(dt_over_tau);
    float sc   = __ldg(sqrt_coeff);
    float sg   = __ldg(sig);
    float m    = __ldg(mu);

    float ib = Iback[i];
    float ib_new = ib + dtau * (noise[i] - ib);
    float ieff = ib_new / sc * sg + m;

    float sv = s[i];
    float s_new = sv + LAMDA_R * (-sv + spike[i] * INV_TAO_D);
    float rv = r[i];
    float r_new = rv - LAMDA_D * rv + DT_C * s_new;

    g_rnew[i] = r_new;
    out[i] = ieff;   // accumulator base (out is poisoned by harness)
}

// ---------------------------------------------------------------------------
// Kernel B: COO edge scatter, 4 edges per thread, 128-bit loads.
//   out[post_e] += w_e * r_new[pre_e]
// edges are INT32 on device (JAX x64 disabled downcasts int64 -> int32):
//   post = edges[0:N_EDGE], pre = edges[N_EDGE:2*N_EDGE]
// r_new (2 MB) and out (2 MB) are L2-resident; atomics compile to REDG.
// ---------------------------------------------------------------------------
__global__ void edge_kernel(const int* __restrict__ post,
                            const int* __restrict__ pre,
                            const float* __restrict__ w,
                            float* __restrict__ out)
{
    int t = blockIdx.x * blockDim.x + threadIdx.x;
    int i = t * 4;
    if (i >= N_EDGE) return;   // N_EDGE % 4 == 0, so full quads only

    int4   p  = *reinterpret_cast<const int4*>(post + i);
    int4   q  = *reinterpret_cast<const int4*>(pre + i);
    float4 ww = *reinterpret_cast<const float4*>(w + i);

    // gather first (maximize MLP), then scatter
    float r0 = __ldg(&g_rnew[q.x]);
    float r1 = __ldg(&g_rnew[q.y]);
    float r2 = __ldg(&g_rnew[q.z]);
    float r3 = __ldg(&g_rnew[q.w]);

    atomicAdd(out + p.x, ww.x * r0);
    atomicAdd(out + p.y, ww.y * r1);
    atomicAdd(out + p.z, ww.z * r2);
    atomicAdd(out + p.w, ww.w * r3);
}

extern "C" void kernel_launch(void* const* d_in, const int* in_sizes, int n_in,
                              void* d_out, int out_size)
{
    const float* weight      = (const float*)d_in[0];
    const int*   edges       = (const int*)d_in[1];   // [2, N_EDGE] int32 (JAX x64 off)
    const float* Iback       = (const float*)d_in[2];
    const float* spike       = (const float*)d_in[3];
    const float* s           = (const float*)d_in[4];
    const float* r           = (const float*)d_in[5];
    const float* noise       = (const float*)d_in[6];
    const float* dt_over_tau = (const float*)d_in[7];
    const float* sqrt_coeff  = (const float*)d_in[8];
    const float* sig         = (const float*)d_in[9];
    const float* mu          = (const float*)d_in[10];
    float* out = (float*)d_out;

    const int* post = edges;
    const int* pre  = edges + N_EDGE;

    int threads = 256;
    int nblocks = (N_NEURON + threads - 1) / threads;
    neuron_kernel<<<nblocks, threads>>>(Iback, spike, s, r, noise,
                                        dt_over_tau, sqrt_coeff, sig, mu, out);

    int nthreads_edge = N_EDGE / 4;
    int eblocks = (nthreads_edge + threads - 1) / threads;
    edge_kernel<<<eblocks, threads>>>(post, pre, weight, out);
}